// round 16
// baseline (speedup 1.0000x reference)
#include <cuda_runtime.h>
#include <cuda_bf16.h>
#include <cstdint>
#include <math.h>

// ---------------- problem constants ----------------
static constexpr int Bn = 32, Cn = 32, Sn = 16, En = 1280, Rn = 256;
static constexpr int Hn = 4, HDn = 64, FFn = 512;
static constexpr int BC = Bn * Cn;               // 1024 tokens
static constexpr int HEAD_IN = Cn * Rn + 64 + 32 + 3;  // 8291
static constexpr int QKVn = 3 * Rn;              // 768
static constexpr int HK = 8192;                  // head GEMM K (aligned part)

static constexpr int NBLK = 592;                 // persistent blocks (4 per SM)
static constexpr int NTHR = 128;                 // one worker group per block
static constexpr int NGRP = NBLK;

static constexpr int LDS_PAD = 40;               // bf16 elems per smem row (32 + 8 pad)
static constexpr int BUFB = 64 * LDS_PAD * 2;    // bytes per smem buffer (5120)

// ---------------- device scratch (fp32) ----------------
__device__ __align__(16) float g_x0p[8 * BC * Rn];    // x0 partials (split 8)
__device__ __align__(16) float g_x0[BC * Rn];         // prereduced x0 (sum8 + br)
__device__ __align__(16) float g_qkvp[2 * BC * QKVn]; // qkv partials (split 2)
__device__ __align__(16) float g_opp[8 * BC * Rn];    // oproj partials (split 8)
__device__ __align__(16) float g_x1[BC * Rn];
__device__ __align__(16) float g_ff1p[4 * BC * FFn];  // ff1 partials (split 4)
__device__ __align__(16) float g_fpp[8 * BC * Rn];    // ff2 partials (split 8)
__device__ __align__(16) float g_hp[128 * 64 * 128];  // head partials (split 128)
__device__ unsigned g_bar[16];                        // monotonic barrier counters
__device__ unsigned g_epoch;                          // launch-epoch counter
__device__ unsigned g_rowcnt[16];                     // per-64-row agg completion (monotonic)
__device__ unsigned g_wrdone;                         // Wr conversion completion (monotonic)

// ---------------- pre-split bf16 activations (hi/lo) ----------------
__device__ __align__(16) unsigned short g_aggH[BC * En],  g_aggL[BC * En];
__device__ __align__(16) unsigned short g_x0H[BC * Rn],   g_x0L[BC * Rn];
__device__ __align__(16) unsigned short g_attH[BC * Rn],  g_attL[BC * Rn];
__device__ __align__(16) unsigned short g_x1H[BC * Rn],   g_x1L[BC * Rn];
__device__ __align__(16) unsigned short g_ff1H[BC * FFn], g_ff1L[BC * FFn];
__device__ __align__(16) unsigned short g_featH[64 * HK], g_featL[64 * HK]; // rows 32-63 stay 0

// ---------------- pre-split bf16 weights (hi/lo) ----------------
__device__ __align__(16) unsigned short g_WrH[Rn * En],    g_WrL[Rn * En];
__device__ __align__(16) unsigned short g_WqH[QKVn * Rn],  g_WqL[QKVn * Rn];
__device__ __align__(16) unsigned short g_WoH[Rn * Rn],    g_WoL[Rn * Rn];
__device__ __align__(16) unsigned short g_W1H[FFn * Rn],   g_W1L[FFn * Rn];
__device__ __align__(16) unsigned short g_W2H[Rn * FFn],   g_W2L[Rn * FFn];
__device__ __align__(16) unsigned short g_WcH[128 * HK],   g_WcL[128 * HK];

// ---------------- shared memory (union across phases) ----------------
struct GemmSmem {
    unsigned short Ah[2][64 * LDS_PAD];
    unsigned short Al[2][64 * LDS_PAD];
    unsigned short Bh[2][64 * LDS_PAD];
    unsigned short Bl[2][64 * LDS_PAD];
};  // 40960 B
struct AttnSmem {
    float ks[32 * 65];
    float vs[32 * 65];
    float qs[16 * 65];
    float sc[16 * 33];
};
union SmemU {
    GemmSmem g;
    AttnSmem a;
};

// ---------------- grid-wide barrier (monotonic, replay-safe) ----------------
__device__ __forceinline__ void gsync(int k) {
    __syncthreads();
    if (threadIdx.x == 0) {
        __threadfence();
        unsigned old = atomicAdd(&g_bar[k], 1u);
        unsigned target = (old / NBLK + 1u) * NBLK;
        volatile unsigned* p = &g_bar[k];
        while (*p < target) { }
        __threadfence();
    }
    __syncthreads();
}

// ---------------- smem address helper ----------------
__device__ __forceinline__ unsigned smem_u32(const void* p) {
    unsigned addr;
    asm("{ .reg .u64 t; cvta.to.shared.u64 t, %1; cvt.u32.u64 %0, t; }"
        : "=r"(addr) : "l"(p));
    return addr;
}

// ---------------- cp.async helpers ----------------
__device__ __forceinline__ void cp16(unsigned dst, const void* src) {
    asm volatile("cp.async.cg.shared.global [%0], [%1], 16;" :: "r"(dst), "l"(src));
}
#define CP_COMMIT() asm volatile("cp.async.commit_group;" ::: "memory")
#define CP_WAIT0()  asm volatile("cp.async.wait_group 0;" ::: "memory")

// ---------------- mma / ldmatrix helpers ----------------
__device__ __forceinline__ void ldsm4(unsigned& r0, unsigned& r1, unsigned& r2, unsigned& r3,
                                      unsigned addr) {
    asm volatile("ldmatrix.sync.aligned.m8n8.x4.shared.b16 {%0,%1,%2,%3}, [%4];"
                 : "=r"(r0), "=r"(r1), "=r"(r2), "=r"(r3) : "r"(addr));
}

__device__ __forceinline__ void mma_bf16(float& c0, float& c1, float& c2, float& c3,
                                         unsigned a0, unsigned a1, unsigned a2, unsigned a3,
                                         unsigned b0, unsigned b1) {
    asm volatile(
        "mma.sync.aligned.m16n8k16.row.col.f32.bf16.bf16.f32 "
        "{%0,%1,%2,%3}, {%4,%5,%6,%7}, {%8,%9}, {%0,%1,%2,%3};"
        : "+f"(c0), "+f"(c1), "+f"(c2), "+f"(c3)
        : "r"(a0), "r"(a1), "r"(a2), "r"(a3), "r"(b0), "r"(b1));
}

__device__ __forceinline__ unsigned bf16bits(float x) {
    return (unsigned)__bfloat16_as_ushort(__float2bfloat16_rn(x));
}
__device__ __forceinline__ float bf16val(unsigned b) {
    return __bfloat162float(__ushort_as_bfloat16((unsigned short)b));
}

// split one float4 into hi/lo packed bf16 pairs (hi = rn(x), lo = rn(x - hi))
__device__ __forceinline__ void split4(float4 v, uint2& hi, uint2& lo) {
    unsigned h0 = bf16bits(v.x), h1 = bf16bits(v.y), h2 = bf16bits(v.z), h3 = bf16bits(v.w);
    unsigned l0 = bf16bits(v.x - bf16val(h0)), l1 = bf16bits(v.y - bf16val(h1));
    unsigned l2 = bf16bits(v.z - bf16val(h2)), l3 = bf16bits(v.w - bf16val(h3));
    hi.x = h0 | (h1 << 16);
    hi.y = h2 | (h3 << 16);
    lo.x = l0 | (l1 << 16);
    lo.y = l2 | (l3 << 16);
}

// scalar split-write
__device__ __forceinline__ void splitw(float v, unsigned short* __restrict__ H,
                                       unsigned short* __restrict__ L, size_t idx) {
    unsigned h = bf16bits(v);
    H[idx] = (unsigned short)h;
    L[idx] = (unsigned short)bf16bits(v - bf16val(h));
}

__device__ __forceinline__ float4 sum2b(const float* __restrict__ P, size_t idx, size_t S,
                                        const float* __restrict__ bias, int bi) {
    float4 a = *(const float4*)(P + idx);
    float4 b = *(const float4*)(P + S + idx);
    float4 c = *(const float4*)(bias + bi);
    a.x += b.x + c.x; a.y += b.y + c.y; a.z += b.z + c.z; a.w += b.w + c.w;
    return a;
}

// ---------------- weight split-conversion ----------------
__device__ void conv_w(const float* __restrict__ src, unsigned short* __restrict__ dh,
                       unsigned short* __restrict__ dl, int n4, int gid0, int gstride) {
    for (int i = gid0; i < n4; i += gstride) {
        float4 v = ((const float4*)src)[i];
        uint2 hi, lo;
        split4(v, hi, lo);
        *(uint2*)(dh + (size_t)i * 4) = hi;
        *(uint2*)(dl + (size_t)i * 4) = lo;
    }
}

// ---------------- shared MMA chunk ----------------
__device__ __forceinline__ void mma_chunk(unsigned aAh, unsigned aAl, unsigned aBh, unsigned aBl,
                                          unsigned bofs, int warp_m, int warp_n,
                                          int lrow, int lblk, float (&acc)[2][4][4]) {
    #pragma unroll
    for (int ks16 = 0; ks16 < 2; ks16++) {
        int ko = ks16 * 16;
        unsigned ah[2][4], al[2][4], bh[2][4], bl[2][4];
        #pragma unroll
        for (int i = 0; i < 2; i++) {
            unsigned o = bofs + (unsigned)(((warp_m + i * 16 + lrow) * LDS_PAD + ko + lblk * 8) * 2);
            ldsm4(ah[i][0], ah[i][1], ah[i][2], ah[i][3], aAh + o);
            ldsm4(al[i][0], al[i][1], al[i][2], al[i][3], aAl + o);
        }
        #pragma unroll
        for (int j = 0; j < 2; j++) {
            unsigned o = bofs + (unsigned)(((warp_n + j * 16 + lrow) * LDS_PAD + ko + lblk * 8) * 2);
            ldsm4(bh[j][0], bh[j][1], bh[j][2], bh[j][3], aBh + o);
            ldsm4(bl[j][0], bl[j][1], bl[j][2], bl[j][3], aBl + o);
        }
        #pragma unroll
        for (int mi = 0; mi < 2; mi++) {
            #pragma unroll
            for (int nj = 0; nj < 2; nj++) {
                #pragma unroll
                for (int h = 0; h < 2; h++) {
                    int ni = nj * 2 + h;
                    mma_bf16(acc[mi][ni][0], acc[mi][ni][1], acc[mi][ni][2], acc[mi][ni][3],
                             ah[mi][0], ah[mi][1], ah[mi][2], ah[mi][3],
                             bh[nj][h], bh[nj][2 + h]);
                    mma_bf16(acc[mi][ni][0], acc[mi][ni][1], acc[mi][ni][2], acc[mi][ni][3],
                             ah[mi][0], ah[mi][1], ah[mi][2], ah[mi][3],
                             bl[nj][h], bl[nj][2 + h]);
                    mma_bf16(acc[mi][ni][0], acc[mi][ni][1], acc[mi][ni][2], acc[mi][ni][3],
                             al[mi][0], al[mi][1], al[mi][2], al[mi][3],
                             bh[nj][h], bh[nj][2 + h]);
                }
            }
        }
    }
}

__device__ __forceinline__ void gemm_epilogue(float* __restrict__ Cout, int N,
                                              int bm0, int bn0, int warp_m, int warp_n,
                                              int quad, int pr, float (&acc)[2][4][4]) {
    #pragma unroll
    for (int mi = 0; mi < 2; mi++) {
        #pragma unroll
        for (int ni = 0; ni < 4; ni++) {
            int mrow = bm0 + warp_m + mi * 16 + quad;
            int ncol = bn0 + warp_n + ni * 8 + pr * 2;
            float2 r0; r0.x = acc[mi][ni][0]; r0.y = acc[mi][ni][1];
            float2 r1; r1.x = acc[mi][ni][2]; r1.y = acc[mi][ni][3];
            *(float2*)&Cout[(size_t)mrow * N + ncol] = r0;
            *(float2*)&Cout[(size_t)(mrow + 8) * N + ncol] = r1;
        }
    }
}

// ---------------- GEMM (SS): A and B pre-split bf16, both via cp.async ----------------
// Optional producer gating: if rc != 0, before each tile spin until
// rc[m] >= rct and *wrf >= wrt (replay-safe monotonic counters).
__device__ void gemm_ss(const unsigned short* __restrict__ AH, const unsigned short* __restrict__ AL,
                        const unsigned short* __restrict__ BH, const unsigned short* __restrict__ BL,
                        float* __restrict__ C, int N, int K, int ntm, int ntn, int nsplit,
                        int KS, int Mrows, GemmSmem* sg, int tid, int grp,
                        const unsigned* rc = 0, unsigned rct = 0,
                        const unsigned* wrf = 0, unsigned wrt = 0) {
    const int ntpz = ntm * ntn;
    const int ntiles = ntpz * nsplit;
    const int warp = tid >> 5, lane = tid & 31;
    const int warp_m = (warp >> 1) * 32, warp_n = (warp & 1) * 32;
    const int lrow = lane & 15, lblk = lane >> 4;
    const int quad = lane >> 2, pr = lane & 3;

    const unsigned aAh = smem_u32(sg->Ah[0]);
    const unsigned aAl = smem_u32(sg->Al[0]);
    const unsigned aBh = smem_u32(sg->Bh[0]);
    const unsigned aBl = smem_u32(sg->Bl[0]);

    const int r0 = tid >> 2, ck0 = (tid & 3) * 8;
    const int r1 = (tid + 128) >> 2, ck1 = ((tid + 128) & 3) * 8;

    int buf = 0;
    for (int tile = grp; tile < ntiles; tile += NGRP) {
        int z = tile / ntpz;
        int rem = tile - z * ntpz;
        int m = rem / ntn, n = rem - m * ntn;
        int bm0 = m * 64, bn0 = n * 64, k0s = z * KS;

        if (rc) {
            if (tid == 0) {
                volatile const unsigned* pm = rc + m;
                while (*pm < rct) { }
                volatile const unsigned* pw = wrf;
                while (*pw < wrt) { }
                __threadfence();
            }
            __syncthreads();
        }

        float acc[2][4][4];
        #pragma unroll
        for (int i = 0; i < 2; i++)
            #pragma unroll
            for (int j = 0; j < 4; j++)
                #pragma unroll
                for (int r = 0; r < 4; r++) { acc[i][j][r] = 0.f; }

        const int nch = KS / 32;
        {
            unsigned d = (unsigned)(buf * BUFB);
            unsigned d0 = d + (unsigned)((r0 * LDS_PAD + ck0) * 2);
            unsigned d1 = d + (unsigned)((r1 * LDS_PAD + ck1) * 2);
            size_t sa0 = (size_t)(bm0 + r0) * K + k0s + ck0;
            size_t sa1 = (size_t)(bm0 + r1) * K + k0s + ck1;
            size_t sb0 = (size_t)(bn0 + r0) * K + k0s + ck0;
            size_t sb1 = (size_t)(bn0 + r1) * K + k0s + ck1;
            cp16(aAh + d0, AH + sa0); cp16(aAl + d0, AL + sa0);
            cp16(aBh + d0, BH + sb0); cp16(aBl + d0, BL + sb0);
            cp16(aAh + d1, AH + sa1); cp16(aAl + d1, AL + sa1);
            cp16(aBh + d1, BH + sb1); cp16(aBl + d1, BL + sb1);
            CP_COMMIT();
        }
        for (int ch = 0; ch < nch; ch++) {
            CP_WAIT0();
            __syncthreads();
            if (ch + 1 < nch) {
                int kc = k0s + (ch + 1) * 32;
                unsigned d = (unsigned)((buf ^ 1) * BUFB);
                unsigned d0 = d + (unsigned)((r0 * LDS_PAD + ck0) * 2);
                unsigned d1 = d + (unsigned)((r1 * LDS_PAD + ck1) * 2);
                size_t sa0 = (size_t)(bm0 + r0) * K + kc + ck0;
                size_t sa1 = (size_t)(bm0 + r1) * K + kc + ck1;
                size_t sb0 = (size_t)(bn0 + r0) * K + kc + ck0;
                size_t sb1 = (size_t)(bn0 + r1) * K + kc + ck1;
                cp16(aAh + d0, AH + sa0); cp16(aAl + d0, AL + sa0);
                cp16(aBh + d0, BH + sb0); cp16(aBl + d0, BL + sb0);
                cp16(aAh + d1, AH + sa1); cp16(aAl + d1, AL + sa1);
                cp16(aBh + d1, BH + sb1); cp16(aBl + d1, BL + sb1);
                CP_COMMIT();
            }
            mma_chunk(aAh, aAl, aBh, aBl, (unsigned)(buf * BUFB),
                      warp_m, warp_n, lrow, lblk, acc);
            buf ^= 1;
        }
        gemm_epilogue(C + (size_t)z * Mrows * N, N, bm0, bn0, warp_m, warp_n, quad, pr, acc);
    }
}

// ---------------- attention worker ----------------
__device__ void attn_phase(AttnSmem* s, const float* __restrict__ bqkv, int tid, int grp) {
    constexpr size_t SQ = (size_t)BC * QKVn;
    for (int u = grp; u < Bn * Hn * 2; u += NGRP) {
        int b = u >> 3, h = (u >> 1) & 3, half = u & 1;
        int q0 = half * 16;
        #pragma unroll
        for (int it = 0; it < 4; it++) {
            int f = tid + it * 128;
            int c = f >> 4, d4 = (f & 15) * 4;
            size_t base = (size_t)(b * Cn + c) * QKVn + h * HDn + d4;
            float4 kv = sum2b(g_qkvp, base + Rn, SQ, bqkv, Rn + h * HDn + d4);
            float4 vv = sum2b(g_qkvp, base + 2 * Rn, SQ, bqkv, 2 * Rn + h * HDn + d4);
            s->ks[c * 65 + d4 + 0] = kv.x; s->ks[c * 65 + d4 + 1] = kv.y;
            s->ks[c * 65 + d4 + 2] = kv.z; s->ks[c * 65 + d4 + 3] = kv.w;
            s->vs[c * 65 + d4 + 0] = vv.x; s->vs[c * 65 + d4 + 1] = vv.y;
            s->vs[c * 65 + d4 + 2] = vv.z; s->vs[c * 65 + d4 + 3] = vv.w;
        }
        #pragma unroll
        for (int it = 0; it < 2; it++) {
            int f = tid + it * 128;
            int c = f >> 4, d4 = (f & 15) * 4;
            size_t base = (size_t)(b * Cn + q0 + c) * QKVn + h * HDn + d4;
            float4 qv = sum2b(g_qkvp, base, SQ, bqkv, h * HDn + d4);
            s->qs[c * 65 + d4 + 0] = qv.x; s->qs[c * 65 + d4 + 1] = qv.y;
            s->qs[c * 65 + d4 + 2] = qv.z; s->qs[c * 65 + d4 + 3] = qv.w;
        }
        __syncthreads();
        #pragma unroll
        for (int r = 0; r < 4; r++) {
            int i = tid + r * 128;
            int k = i & 31, q = i >> 5;
            float sum = 0.f;
            #pragma unroll
            for (int d = 0; d < HDn; d++) { sum = fmaf(s->qs[q * 65 + d], s->ks[k * 65 + d], sum); }
            s->sc[q * 33 + k] = sum * 0.125f;
        }
        __syncthreads();
        if (tid < 16) {
            float mx = -1e30f;
            #pragma unroll
            for (int k = 0; k < Cn; k++) { mx = fmaxf(mx, s->sc[tid * 33 + k]); }
            float sum = 0.f;
            #pragma unroll
            for (int k = 0; k < Cn; k++) {
                float e = expf(s->sc[tid * 33 + k] - mx);
                s->sc[tid * 33 + k] = e;
                sum += e;
            }
            float inv = 1.f / sum;
            #pragma unroll
            for (int k = 0; k < Cn; k++) { s->sc[tid * 33 + k] *= inv; }
        }
        __syncthreads();
        #pragma unroll
        for (int r = 0; r < 8; r++) {
            int i = tid + r * 128;
            int d = i & 63, q = i >> 6;
            float sum = 0.f;
            #pragma unroll
            for (int k = 0; k < Cn; k++) { sum = fmaf(s->sc[q * 33 + k], s->vs[k * 65 + d], sum); }
            splitw(sum, g_attH, g_attL, (size_t)(b * Cn + q0 + q) * Rn + h * HDn + d);
        }
        __syncthreads();   // smem reused by next unit
    }
}

// ---------------- LayerNorm worker: one warp per row ----------------
template <int NPA, int NPP, bool WF32>
__device__ void ln_phase(const float* __restrict__ a, const float* __restrict__ ab,
                         const float* __restrict__ p, const float* __restrict__ pb,
                         const float* __restrict__ g, const float* __restrict__ be,
                         float* __restrict__ outF,
                         unsigned short* __restrict__ outH, unsigned short* __restrict__ outL) {
    int row = blockIdx.x * (NTHR / 32) + (threadIdx.x >> 5);
    if (row >= BC) { return; }
    const size_t S = (size_t)BC * Rn;
    int lane = threadIdx.x & 31;
    float v[8];
    #pragma unroll
    for (int j = 0; j < 8; j++) {
        int c = lane + 32 * j;
        size_t o = (size_t)row * Rn + c;
        float x = a[o];
        if (NPA >= 4) { x += a[S + o] + a[2 * S + o] + a[3 * S + o]; }
        if (NPA >= 8) {
            #pragma unroll
            for (int z = 4; z < 8; z++) { x += a[(size_t)z * S + o]; }
        }
        if (NPA > 1) { x += ab[c]; }
        float y = p[o];
        if (NPP >= 2) { y += p[S + o]; }
        if (NPP >= 4) { y += p[2 * S + o] + p[3 * S + o]; }
        if (NPP >= 8) {
            #pragma unroll
            for (int z = 4; z < 8; z++) { y += p[(size_t)z * S + o]; }
        }
        v[j] = x + y + pb[c];
    }
    float sum = 0.f;
    #pragma unroll
    for (int j = 0; j < 8; j++) { sum += v[j]; }
    #pragma unroll
    for (int off = 16; off > 0; off >>= 1) { sum += __shfl_xor_sync(0xffffffffu, sum, off); }
    float mean = sum * (1.f / Rn);
    float q = 0.f;
    #pragma unroll
    for (int j = 0; j < 8; j++) { float d = v[j] - mean; q = fmaf(d, d, q); }
    #pragma unroll
    for (int off = 16; off > 0; off >>= 1) { q += __shfl_xor_sync(0xffffffffu, q, off); }
    float rstd = rsqrtf(q * (1.f / Rn) + 1e-5f);
    #pragma unroll
    for (int j = 0; j < 8; j++) {
        int c = lane + 32 * j;
        float r = (v[j] - mean) * rstd * g[c] + be[c];
        size_t o = (size_t)row * Rn + c;
        if (WF32) { outF[o] = r; }
        splitw(r, outH, outL, o);
    }
}

// ---------------- megakernel ----------------
__global__ __launch_bounds__(NTHR, 4)
void mega_kernel(const float* __restrict__ embs, const int* __restrict__ indices,
                 const int* __restrict__ mask, const float* __restrict__ host_cat,
                 const float* __restrict__ virus_cat, const float* __restrict__ extra_meta,
                 const float* __restrict__ fw,
                 const float* __restrict__ Wr, const float* __restrict__ br,
                 const float* __restrict__ Wqkv, const float* __restrict__ bqkv,
                 const float* __restrict__ Wo, const float* __restrict__ bo,
                 const float* __restrict__ ln1_g, const float* __restrict__ ln1_b,
                 const float* __restrict__ W1, const float* __restrict__ b1,
                 const float* __restrict__ W2, const float* __restrict__ b2,
                 const float* __restrict__ ln2_g, const float* __restrict__ ln2_b,
                 const float* __restrict__ Wc1, const float* __restrict__ bc1,
                 const float* __restrict__ Wc2, const float* __restrict__ bc2,
                 float* __restrict__ out) {
    __shared__ SmemU sm;
    __shared__ float s_red[4];
    __shared__ float s_aw[Sn];
    __shared__ unsigned s_epoch;
    const int tid = threadIdx.x;
    const int grp = blockIdx.x;
    const int gid = blockIdx.x * NTHR + tid;
    const int lane = tid & 31;

    // ---- epoch (replay-safe; all blocks of one launch agree) ----
    if (tid == 0) { s_epoch = atomicAdd(&g_epoch, 1u) / NBLK; }
    __syncthreads();
    const unsigned epoch = s_epoch;

    // ---- P0a: Wr conversion first (signals g_wrdone) ----
    conv_w(Wr, g_WrH, g_WrL, Rn * En / 4, gid, NBLK * NTHR);
    __syncthreads();
    if (tid == 0) {
        __threadfence();
        atomicAdd(&g_wrdone, 1u);
    }

    // ---- P0b: aggregation, half-segment units (2048), signals g_rowcnt[seg>>6] ----
    for (int u = grp; u < 2 * BC; u += NGRP) {
        int seg = u >> 1;
        int half = u & 1;
        if (tid < 32) {
            int s16 = lane & 15;
            int mval = mask[seg * Sn + s16];
            float wv = mval ? fw[indices[seg * Sn + s16]] : -1e30f;
            unsigned anyb = __ballot_sync(0xffffffffu, mval != 0);
            float mx = wv;
            #pragma unroll
            for (int off = 8; off > 0; off >>= 1) { mx = fmaxf(mx, __shfl_xor_sync(0xffffffffu, mx, off)); }
            float e = expf(wv - mx);
            float esum = e;
            #pragma unroll
            for (int off = 8; off > 0; off >>= 1) { esum += __shfl_xor_sync(0xffffffffu, esum, off); }
            float myw = (anyb & 0xffffu) ? (e / esum) : 0.f;
            if (lane < 16) { s_aw[lane] = myw; }
        }
        __syncthreads();
        float w[Sn];
        #pragma unroll
        for (int s = 0; s < Sn; s++) { w[s] = s_aw[s]; }
        const float4* eb = (const float4*)embs + (size_t)seg * Sn * (En / 4);
        const int c0 = half * 160, c1 = c0 + 160;
        for (int col = c0 + tid; col < c1; col += NTHR) {
            float4 acc;
            acc.x = 0.f; acc.y = 0.f; acc.z = 0.f; acc.w = 0.f;
            #pragma unroll
            for (int s = 0; s < Sn; s++) {
                float4 v = eb[s * (En / 4) + col];
                acc.x = fmaf(w[s], v.x, acc.x);
                acc.y = fmaf(w[s], v.y, acc.y);
                acc.z = fmaf(w[s], v.z, acc.z);
                acc.w = fmaf(w[s], v.w, acc.w);
            }
            uint2 hi, lo;
            split4(acc, hi, lo);
            *(uint2*)(g_aggH + (size_t)seg * En + col * 4) = hi;
            *(uint2*)(g_aggL + (size_t)seg * En + col * 4) = lo;
        }
        __syncthreads();   // unit complete (s_aw reuse + all stores issued)
        if (tid == 0) {
            __threadfence();
            atomicAdd(&g_rowcnt[seg >> 6], 1u);
        }
    }

    // ---- P2: x0 partials = agg @ Wr^T (gated on rowcnt/wrdone; no gsync before!) ----
    gemm_ss(g_aggH, g_aggL, g_WrH, g_WrL, g_x0p, Rn, En, 16, 4, 8, 160, BC, &sm.g, tid, grp,
            g_rowcnt, 128u * (epoch + 1u), &g_wrdone, (unsigned)NBLK * (epoch + 1u));
    if (grp >= 512) {   // idle groups convert Wqkv (needed at P3)
        conv_w(Wqkv, g_WqH, g_WqL, QKVn * Rn / 4, (grp - 512) * NTHR + tid, 80 * NTHR);
    }
    gsync(1);

    // ---- R1: x0 = sum8(x0p) + br  -> fp32 + bf16 split ----
    {
        constexpr size_t S = (size_t)BC * Rn;
        for (int i = gid; i < BC * Rn / 4; i += NBLK * NTHR) {
            size_t o = (size_t)i * 4;
            float4 v = *(const float4*)(g_x0p + o);
            #pragma unroll
            for (int z = 1; z < 8; z++) {
                float4 t = *(const float4*)(g_x0p + (size_t)z * S + o);
                v.x += t.x; v.y += t.y; v.z += t.z; v.w += t.w;
            }
            float4 bb = *(const float4*)(br + (i & 63) * 4);
            v.x += bb.x; v.y += bb.y; v.z += bb.z; v.w += bb.w;
            *(float4*)(g_x0 + o) = v;
            uint2 hi, lo;
            split4(v, hi, lo);
            *(uint2*)(g_x0H + o) = hi;
            *(uint2*)(g_x0L + o) = lo;
        }
    }
    gsync(2);

    // ---- P3: qkv partials = x0 @ Wqkv^T (SS, split 2, KS=128, 384 tiles) ----
    gemm_ss(g_x0H, g_x0L, g_WqH, g_WqL, g_qkvp, QKVn, Rn, 16, 12, 2, 128, BC, &sm.g, tid, grp);
    if (grp >= 384) {   // idle groups convert Wo (needed at P5)
        conv_w(Wo, g_WoH, g_WoL, Rn * Rn / 4, (grp - 384) * NTHR + tid, 208 * NTHR);
    }
    gsync(3);

    // ---- P4: attention (256 units); idle groups convert W1, W2, Wc1 ----
    attn_phase(&sm.a, bqkv, tid, grp);
    if (grp >= 256) {
        int base = (grp - 256) * NTHR + tid;
        int stride = 336 * NTHR;
        conv_w(W1, g_W1H, g_W1L, FFn * Rn / 4, base, stride);
        conv_w(W2, g_W2H, g_W2L, Rn * FFn / 4, base, stride);
        for (int i = base; i < 128 * (HK / 4); i += stride) {
            int row = i >> 11;
            int c4 = (i & 2047) * 4;
            const float* sp = Wc1 + (size_t)row * HEAD_IN + c4;
            float4 v;
            v.x = sp[0]; v.y = sp[1]; v.z = sp[2]; v.w = sp[3];
            uint2 hi, lo;
            split4(v, hi, lo);
            *(uint2*)(g_WcH + (size_t)row * HK + c4) = hi;
            *(uint2*)(g_WcL + (size_t)row * HK + c4) = lo;
        }
    }
    gsync(4);

    // ---- P5: oproj partials = att @ Wo^T (SS, split 8, KS=32, 1 chunk, 512 tiles) ----
    gemm_ss(g_attH, g_attL, g_WoH, g_WoL, g_opp, Rn, Rn, 16, 4, 8, 32, BC, &sm.g, tid, grp);
    gsync(5);

    // ---- P6: x1 = LN(x0 + sum8 opp + bo), write fp32 + split ----
    ln_phase<1, 8, true>(g_x0, (const float*)0, g_opp, bo, ln1_g, ln1_b, g_x1, g_x1H, g_x1L);
    gsync(6);

    // ---- P7: ff1 partials = x1 @ W1^T (SS, split 4, KS=64, 2 chunks, 512 tiles) ----
    gemm_ss(g_x1H, g_x1L, g_W1H, g_W1L, g_ff1p, FFn, Rn, 16, 8, 4, 64, BC, &sm.g, tid, grp);
    gsync(7);

    // ---- R2: ff1s = relu(sum4(ff1p) + b1) -> bf16 split ----
    {
        constexpr size_t S = (size_t)BC * FFn;
        for (int i = gid; i < BC * FFn / 4; i += NBLK * NTHR) {
            size_t o = (size_t)i * 4;
            float4 v = *(const float4*)(g_ff1p + o);
            #pragma unroll
            for (int z = 1; z < 4; z++) {
                float4 t = *(const float4*)(g_ff1p + (size_t)z * S + o);
                v.x += t.x; v.y += t.y; v.z += t.z; v.w += t.w;
            }
            float4 bb = *(const float4*)(b1 + (i & 127) * 4);
            v.x = fmaxf(v.x + bb.x, 0.f);
            v.y = fmaxf(v.y + bb.y, 0.f);
            v.z = fmaxf(v.z + bb.z, 0.f);
            v.w = fmaxf(v.w + bb.w, 0.f);
            uint2 hi, lo;
            split4(v, hi, lo);
            *(uint2*)(g_ff1H + o) = hi;
            *(uint2*)(g_ff1L + o) = lo;
        }
    }
    gsync(8);

    // ---- P8: ff2 partials = ff1s @ W2^T (SS, split 8, KS=64, 2 chunks, 512 tiles) ----
    gemm_ss(g_ff1H, g_ff1L, g_W2H, g_W2L, g_fpp, Rn, FFn, 16, 4, 8, 64, BC, &sm.g, tid, grp);
    gsync(9);

    // ---- P9: x2 = LN(x1 + sum8 fpp + b2) -> feat split rows 0-31 ([32, 8192] flat) ----
    ln_phase<1, 8, false>(g_x1, (const float*)0, g_fpp, b2, ln2_g, ln2_b,
                          (float*)0, g_featH, g_featL);
    gsync(10);

    // ---- P10: head GEMM: hp = feat[64, 8192] @ Wc1h[128, 8192]^T (SS, split 128, KS=64) ----
    gemm_ss(g_featH, g_featL, g_WcH, g_WcL, g_hp, 128, HK, 1, 2, 128, 64, 64, &sm.g, tid, grp);
    gsync(11);

    // ---- P11: head reduce + tail + bias + relu + logits (block b = batch b) ----
    if (grp < Bn) {
        int b = grp;
        int j = tid;
        float s = 0.f;
        #pragma unroll 16
        for (int z = 0; z < 128; z++) { s += g_hp[(size_t)z * (64 * 128) + b * 128 + j]; }
        const float* wr = Wc1 + (size_t)j * HEAD_IN + HK;
        const float* hc = host_cat + b * 64;
        #pragma unroll 8
        for (int i = 0; i < 64; i++) { s = fmaf(wr[i], hc[i], s); }
        const float* vc = virus_cat + b * 32;
        #pragma unroll 8
        for (int i = 0; i < 32; i++) { s = fmaf(wr[64 + i], vc[i], s); }
        const float* mt = extra_meta + b * 3;
        for (int i = 0; i < 3; i++) { s = fmaf(wr[96 + i], mt[i], s); }
        float hval = fmaxf(s + bc1[j], 0.f);
        float v = hval * Wc2[j];
        #pragma unroll
        for (int off = 16; off > 0; off >>= 1) { v += __shfl_xor_sync(0xffffffffu, v, off); }
        if (lane == 0) { s_red[tid >> 5] = v; }
        __syncthreads();
        if (tid == 0) { out[b] = s_red[0] + s_red[1] + s_red[2] + s_red[3] + bc2[0]; }
    }
}

// ---------------- launch ----------------
extern "C" void kernel_launch(void* const* d_in, const int* in_sizes, int n_in,
                              void* d_out, int out_size) {
    const float* embs        = (const float*)d_in[0];
    const int*   indices     = (const int*)d_in[1];
    const int*   mask        = (const int*)d_in[2];     // bool -> int32
    const float* host_cat    = (const float*)d_in[3];
    const float* virus_cat   = (const float*)d_in[4];
    const float* extra_meta  = (const float*)d_in[5];
    const float* func_weights= (const float*)d_in[6];
    const float* Wr          = (const float*)d_in[7];
    const float* br          = (const float*)d_in[8];
    const float* Wqkv        = (const float*)d_in[9];
    const float* bqkv        = (const float*)d_in[10];
    const float* Wo          = (const float*)d_in[11];
    const float* bo          = (const float*)d_in[12];
    const float* ln1_g       = (const float*)d_in[13];
    const float* ln1_b       = (const float*)d_in[14];
    const float* W1          = (const float*)d_in[15];
    const float* b1          = (const float*)d_in[16];
    const float* W2          = (const float*)d_in[17];
    const float* b2          = (const float*)d_in[18];
    const float* ln2_g       = (const float*)d_in[19];
    const float* ln2_b       = (const float*)d_in[20];
    const float* Wc1         = (const float*)d_in[21];
    const float* bc1         = (const float*)d_in[22];
    const float* Wc2         = (const float*)d_in[23];
    const float* bc2         = (const float*)d_in[24];
    float* out = (float*)d_out;

    mega_kernel<<<NBLK, NTHR>>>(embs, indices, mask, host_cat, virus_cat, extra_meta,
                                func_weights, Wr, br, Wqkv, bqkv, Wo, bo,
                                ln1_g, ln1_b, W1, b1, W2, b2, ln2_g, ln2_b,
                                Wc1, bc1, Wc2, bc2, out);
}

// round 17
// speedup vs baseline: 1.0206x; 1.0206x over previous
#include <cuda_runtime.h>
#include <cuda_bf16.h>
#include <cstdint>
#include <math.h>

// ---------------- problem constants ----------------
static constexpr int Bn = 32, Cn = 32, Sn = 16, En = 1280, Rn = 256;
static constexpr int Hn = 4, HDn = 64, FFn = 512;
static constexpr int BC = Bn * Cn;               // 1024 tokens
static constexpr int HEAD_IN = Cn * Rn + 64 + 32 + 3;  // 8291
static constexpr int QKVn = 3 * Rn;              // 768
static constexpr int HK = 8192;                  // head GEMM K (aligned part)

static constexpr int NBLK = 592;                 // persistent blocks (4 per SM)
static constexpr int NTHR = 128;                 // one worker group per block
static constexpr int NGRP = NBLK;

static constexpr int LDS_PAD = 40;               // bf16 elems per smem row (32 + 8 pad)
static constexpr int BUFB = 64 * LDS_PAD * 2;    // bytes per smem buffer (5120)

// ---------------- device scratch (fp32) ----------------
__device__ __align__(16) float g_x0p[8 * BC * Rn];    // x0 partials (split 8)
__device__ __align__(16) float g_x0[BC * Rn];         // prereduced x0 (sum8 + br)
__device__ __align__(16) float g_qkvp[2 * BC * QKVn]; // qkv partials (split 2)
__device__ __align__(16) float g_opp[8 * BC * Rn];    // oproj partials (split 8)
__device__ __align__(16) float g_x1[BC * Rn];
__device__ __align__(16) float g_ff1p[4 * BC * FFn];  // ff1 partials (split 4)
__device__ __align__(16) float g_fpp[8 * BC * Rn];    // ff2 partials (split 8)
__device__ __align__(16) float g_hp[128 * 64 * 128];  // head partials (split 128)
__device__ unsigned g_bar[16];                        // monotonic barrier counters

// ---------------- pre-split bf16 activations (hi/lo) ----------------
__device__ __align__(16) unsigned short g_aggH[BC * En],  g_aggL[BC * En];
__device__ __align__(16) unsigned short g_x0H[BC * Rn],   g_x0L[BC * Rn];
__device__ __align__(16) unsigned short g_attH[BC * Rn],  g_attL[BC * Rn];
__device__ __align__(16) unsigned short g_x1H[BC * Rn],   g_x1L[BC * Rn];
__device__ __align__(16) unsigned short g_ff1H[BC * FFn], g_ff1L[BC * FFn];
__device__ __align__(16) unsigned short g_featH[64 * HK], g_featL[64 * HK]; // rows 32-63 stay 0

// ---------------- pre-split bf16 weights (hi/lo) ----------------
__device__ __align__(16) unsigned short g_WrH[Rn * En],    g_WrL[Rn * En];
__device__ __align__(16) unsigned short g_WqH[QKVn * Rn],  g_WqL[QKVn * Rn];
__device__ __align__(16) unsigned short g_WoH[Rn * Rn],    g_WoL[Rn * Rn];
__device__ __align__(16) unsigned short g_W1H[FFn * Rn],   g_W1L[FFn * Rn];
__device__ __align__(16) unsigned short g_W2H[Rn * FFn],   g_W2L[Rn * FFn];
__device__ __align__(16) unsigned short g_WcH[128 * HK],   g_WcL[128 * HK];

// ---------------- shared memory (union across phases) ----------------
struct GemmSmem {
    unsigned short Ah[2][64 * LDS_PAD];
    unsigned short Al[2][64 * LDS_PAD];
    unsigned short Bh[2][64 * LDS_PAD];
    unsigned short Bl[2][64 * LDS_PAD];
};  // 40960 B
struct AttnSmem {
    float ks[32 * 65];
    float vs[32 * 65];
    float qs[16 * 65];
    float sc[16 * 33];
};
union SmemU {
    GemmSmem g;
    AttnSmem a;
};

// ---------------- grid-wide barrier (monotonic, replay-safe) ----------------
__device__ __forceinline__ void gsync(int k) {
    __syncthreads();
    if (threadIdx.x == 0) {
        __threadfence();
        unsigned old = atomicAdd(&g_bar[k], 1u);
        unsigned target = (old / NBLK + 1u) * NBLK;
        volatile unsigned* p = &g_bar[k];
        while (*p < target) { }
        __threadfence();
    }
    __syncthreads();
}

// ---------------- smem address helper ----------------
__device__ __forceinline__ unsigned smem_u32(const void* p) {
    unsigned addr;
    asm("{ .reg .u64 t; cvta.to.shared.u64 t, %1; cvt.u32.u64 %0, t; }"
        : "=r"(addr) : "l"(p));
    return addr;
}

// ---------------- cp.async helpers ----------------
__device__ __forceinline__ void cp16(unsigned dst, const void* src) {
    asm volatile("cp.async.cg.shared.global [%0], [%1], 16;" :: "r"(dst), "l"(src));
}
#define CP_COMMIT() asm volatile("cp.async.commit_group;" ::: "memory")
#define CP_WAIT0()  asm volatile("cp.async.wait_group 0;" ::: "memory")
#define CP_WAIT1()  asm volatile("cp.async.wait_group 1;" ::: "memory")

// ---------------- mma / ldmatrix helpers ----------------
__device__ __forceinline__ void ldsm4(unsigned& r0, unsigned& r1, unsigned& r2, unsigned& r3,
                                      unsigned addr) {
    asm volatile("ldmatrix.sync.aligned.m8n8.x4.shared.b16 {%0,%1,%2,%3}, [%4];"
                 : "=r"(r0), "=r"(r1), "=r"(r2), "=r"(r3) : "r"(addr));
}

__device__ __forceinline__ void mma_bf16(float& c0, float& c1, float& c2, float& c3,
                                         unsigned a0, unsigned a1, unsigned a2, unsigned a3,
                                         unsigned b0, unsigned b1) {
    asm volatile(
        "mma.sync.aligned.m16n8k16.row.col.f32.bf16.bf16.f32 "
        "{%0,%1,%2,%3}, {%4,%5,%6,%7}, {%8,%9}, {%0,%1,%2,%3};"
        : "+f"(c0), "+f"(c1), "+f"(c2), "+f"(c3)
        : "r"(a0), "r"(a1), "r"(a2), "r"(a3), "r"(b0), "r"(b1));
}

__device__ __forceinline__ unsigned bf16bits(float x) {
    return (unsigned)__bfloat16_as_ushort(__float2bfloat16_rn(x));
}
__device__ __forceinline__ float bf16val(unsigned b) {
    return __bfloat162float(__ushort_as_bfloat16((unsigned short)b));
}

// split one float4 into hi/lo packed bf16 pairs (hi = rn(x), lo = rn(x - hi))
__device__ __forceinline__ void split4(float4 v, uint2& hi, uint2& lo) {
    unsigned h0 = bf16bits(v.x), h1 = bf16bits(v.y), h2 = bf16bits(v.z), h3 = bf16bits(v.w);
    unsigned l0 = bf16bits(v.x - bf16val(h0)), l1 = bf16bits(v.y - bf16val(h1));
    unsigned l2 = bf16bits(v.z - bf16val(h2)), l3 = bf16bits(v.w - bf16val(h3));
    hi.x = h0 | (h1 << 16);
    hi.y = h2 | (h3 << 16);
    lo.x = l0 | (l1 << 16);
    lo.y = l2 | (l3 << 16);
}

// scalar split-write
__device__ __forceinline__ void splitw(float v, unsigned short* __restrict__ H,
                                       unsigned short* __restrict__ L, size_t idx) {
    unsigned h = bf16bits(v);
    H[idx] = (unsigned short)h;
    L[idx] = (unsigned short)bf16bits(v - bf16val(h));
}

__device__ __forceinline__ float4 sum2b(const float* __restrict__ P, size_t idx, size_t S,
                                        const float* __restrict__ bias, int bi) {
    float4 a = *(const float4*)(P + idx);
    float4 b = *(const float4*)(P + S + idx);
    float4 c = *(const float4*)(bias + bi);
    a.x += b.x + c.x; a.y += b.y + c.y; a.z += b.z + c.z; a.w += b.w + c.w;
    return a;
}

// ---------------- weight split-conversion ----------------
__device__ void conv_w(const float* __restrict__ src, unsigned short* __restrict__ dh,
                       unsigned short* __restrict__ dl, int n4, int gid0, int gstride) {
    for (int i = gid0; i < n4; i += gstride) {
        float4 v = ((const float4*)src)[i];
        uint2 hi, lo;
        split4(v, hi, lo);
        *(uint2*)(dh + (size_t)i * 4) = hi;
        *(uint2*)(dl + (size_t)i * 4) = lo;
    }
}

// ---------------- shared MMA chunk ----------------
__device__ __forceinline__ void mma_chunk(unsigned aAh, unsigned aAl, unsigned aBh, unsigned aBl,
                                          unsigned bofs, int warp_m, int warp_n,
                                          int lrow, int lblk, float (&acc)[2][4][4]) {
    #pragma unroll
    for (int ks16 = 0; ks16 < 2; ks16++) {
        int ko = ks16 * 16;
        unsigned ah[2][4], al[2][4], bh[2][4], bl[2][4];
        #pragma unroll
        for (int i = 0; i < 2; i++) {
            unsigned o = bofs + (unsigned)(((warp_m + i * 16 + lrow) * LDS_PAD + ko + lblk * 8) * 2);
            ldsm4(ah[i][0], ah[i][1], ah[i][2], ah[i][3], aAh + o);
            ldsm4(al[i][0], al[i][1], al[i][2], al[i][3], aAl + o);
        }
        #pragma unroll
        for (int j = 0; j < 2; j++) {
            unsigned o = bofs + (unsigned)(((warp_n + j * 16 + lrow) * LDS_PAD + ko + lblk * 8) * 2);
            ldsm4(bh[j][0], bh[j][1], bh[j][2], bh[j][3], aBh + o);
            ldsm4(bl[j][0], bl[j][1], bl[j][2], bl[j][3], aBl + o);
        }
        #pragma unroll
        for (int mi = 0; mi < 2; mi++) {
            #pragma unroll
            for (int nj = 0; nj < 2; nj++) {
                #pragma unroll
                for (int h = 0; h < 2; h++) {
                    int ni = nj * 2 + h;
                    mma_bf16(acc[mi][ni][0], acc[mi][ni][1], acc[mi][ni][2], acc[mi][ni][3],
                             ah[mi][0], ah[mi][1], ah[mi][2], ah[mi][3],
                             bh[nj][h], bh[nj][2 + h]);
                    mma_bf16(acc[mi][ni][0], acc[mi][ni][1], acc[mi][ni][2], acc[mi][ni][3],
                             ah[mi][0], ah[mi][1], ah[mi][2], ah[mi][3],
                             bl[nj][h], bl[nj][2 + h]);
                    mma_bf16(acc[mi][ni][0], acc[mi][ni][1], acc[mi][ni][2], acc[mi][ni][3],
                             al[mi][0], al[mi][1], al[mi][2], al[mi][3],
                             bh[nj][h], bh[nj][2 + h]);
                }
            }
        }
    }
}

__device__ __forceinline__ void gemm_epilogue(float* __restrict__ Cout, int N,
                                              int bm0, int bn0, int warp_m, int warp_n,
                                              int quad, int pr, float (&acc)[2][4][4]) {
    #pragma unroll
    for (int mi = 0; mi < 2; mi++) {
        #pragma unroll
        for (int ni = 0; ni < 4; ni++) {
            int mrow = bm0 + warp_m + mi * 16 + quad;
            int ncol = bn0 + warp_n + ni * 8 + pr * 2;
            float2 r0; r0.x = acc[mi][ni][0]; r0.y = acc[mi][ni][1];
            float2 r1; r1.x = acc[mi][ni][2]; r1.y = acc[mi][ni][3];
            *(float2*)&Cout[(size_t)mrow * N + ncol] = r0;
            *(float2*)&Cout[(size_t)(mrow + 8) * N + ncol] = r1;
        }
    }
}

// ---------------- GEMM (SS): A and B pre-split bf16, both via cp.async ----------------
// Improved schedule: issue chunk ch+1 BEFORE waiting on chunk ch (wait_group<=1),
// so the next fetch overlaps wait+sync+compute, not just compute.
__device__ void gemm_ss(const unsigned short* __restrict__ AH, const unsigned short* __restrict__ AL,
                        const unsigned short* __restrict__ BH, const unsigned short* __restrict__ BL,
                        float* __restrict__ C, int N, int K, int ntm, int ntn, int nsplit,
                        int KS, int Mrows, GemmSmem* sg, int tid, int grp) {
    const int ntpz = ntm * ntn;
    const int ntiles = ntpz * nsplit;
    const int warp = tid >> 5, lane = tid & 31;
    const int warp_m = (warp >> 1) * 32, warp_n = (warp & 1) * 32;
    const int lrow = lane & 15, lblk = lane >> 4;
    const int quad = lane >> 2, pr = lane & 3;

    const unsigned aAh = smem_u32(sg->Ah[0]);
    const unsigned aAl = smem_u32(sg->Al[0]);
    const unsigned aBh = smem_u32(sg->Bh[0]);
    const unsigned aBl = smem_u32(sg->Bl[0]);

    const int r0 = tid >> 2, ck0 = (tid & 3) * 8;
    const int r1 = (tid + 128) >> 2, ck1 = ((tid + 128) & 3) * 8;

    int buf = 0;
    for (int tile = grp; tile < ntiles; tile += NGRP) {
        int z = tile / ntpz;
        int rem = tile - z * ntpz;
        int m = rem / ntn, n = rem - m * ntn;
        int bm0 = m * 64, bn0 = n * 64, k0s = z * KS;

        float acc[2][4][4];
        #pragma unroll
        for (int i = 0; i < 2; i++)
            #pragma unroll
            for (int j = 0; j < 4; j++)
                #pragma unroll
                for (int r = 0; r < 4; r++) { acc[i][j][r] = 0.f; }

        const int nch = KS / 32;
        // issue chunk 0 into current buf
        {
            unsigned d = (unsigned)(buf * BUFB);
            unsigned d0 = d + (unsigned)((r0 * LDS_PAD + ck0) * 2);
            unsigned d1 = d + (unsigned)((r1 * LDS_PAD + ck1) * 2);
            size_t sa0 = (size_t)(bm0 + r0) * K + k0s + ck0;
            size_t sa1 = (size_t)(bm0 + r1) * K + k0s + ck1;
            size_t sb0 = (size_t)(bn0 + r0) * K + k0s + ck0;
            size_t sb1 = (size_t)(bn0 + r1) * K + k0s + ck1;
            cp16(aAh + d0, AH + sa0); cp16(aAl + d0, AL + sa0);
            cp16(aBh + d0, BH + sb0); cp16(aBl + d0, BL + sb0);
            cp16(aAh + d1, AH + sa1); cp16(aAl + d1, AL + sa1);
            cp16(aBh + d1, BH + sb1); cp16(aBl + d1, BL + sb1);
            CP_COMMIT();
        }
        for (int ch = 0; ch < nch; ch++) {
            const bool has = (ch + 1) < nch;
            if (has) {
                // issue next chunk BEFORE waiting (previous compute of buf^1 finished
                // at the trailing sync of the prior iteration)
                int kc = k0s + (ch + 1) * 32;
                unsigned d = (unsigned)((buf ^ 1) * BUFB);
                unsigned d0 = d + (unsigned)((r0 * LDS_PAD + ck0) * 2);
                unsigned d1 = d + (unsigned)((r1 * LDS_PAD + ck1) * 2);
                size_t sa0 = (size_t)(bm0 + r0) * K + kc + ck0;
                size_t sa1 = (size_t)(bm0 + r1) * K + kc + ck1;
                size_t sb0 = (size_t)(bn0 + r0) * K + kc + ck0;
                size_t sb1 = (size_t)(bn0 + r1) * K + kc + ck1;
                cp16(aAh + d0, AH + sa0); cp16(aAl + d0, AL + sa0);
                cp16(aBh + d0, BH + sb0); cp16(aBl + d0, BL + sb0);
                cp16(aAh + d1, AH + sa1); cp16(aAl + d1, AL + sa1);
                cp16(aBh + d1, BH + sb1); cp16(aBl + d1, BL + sb1);
                CP_COMMIT();
                CP_WAIT1();   // chunk ch complete; ch+1 may still be in flight
            } else {
                CP_WAIT0();
            }
            __syncthreads();      // everyone's chunk-ch data visible
            mma_chunk(aAh, aAl, aBh, aBl, (unsigned)(buf * BUFB),
                      warp_m, warp_n, lrow, lblk, acc);
            __syncthreads();      // protect buf (refilled next iteration) from stragglers
            buf ^= 1;
        }
        gemm_epilogue(C + (size_t)z * Mrows * N, N, bm0, bn0, warp_m, warp_n, quad, pr, acc);
    }
}

// ---------------- attention worker ----------------
__device__ void attn_phase(AttnSmem* s, const float* __restrict__ bqkv, int tid, int grp) {
    constexpr size_t SQ = (size_t)BC * QKVn;
    for (int u = grp; u < Bn * Hn * 2; u += NGRP) {
        int b = u >> 3, h = (u >> 1) & 3, half = u & 1;
        int q0 = half * 16;
        #pragma unroll
        for (int it = 0; it < 4; it++) {
            int f = tid + it * 128;
            int c = f >> 4, d4 = (f & 15) * 4;
            size_t base = (size_t)(b * Cn + c) * QKVn + h * HDn + d4;
            float4 kv = sum2b(g_qkvp, base + Rn, SQ, bqkv, Rn + h * HDn + d4);
            float4 vv = sum2b(g_qkvp, base + 2 * Rn, SQ, bqkv, 2 * Rn + h * HDn + d4);
            s->ks[c * 65 + d4 + 0] = kv.x; s->ks[c * 65 + d4 + 1] = kv.y;
            s->ks[c * 65 + d4 + 2] = kv.z; s->ks[c * 65 + d4 + 3] = kv.w;
            s->vs[c * 65 + d4 + 0] = vv.x; s->vs[c * 65 + d4 + 1] = vv.y;
            s->vs[c * 65 + d4 + 2] = vv.z; s->vs[c * 65 + d4 + 3] = vv.w;
        }
        #pragma unroll
        for (int it = 0; it < 2; it++) {
            int f = tid + it * 128;
            int c = f >> 4, d4 = (f & 15) * 4;
            size_t base = (size_t)(b * Cn + q0 + c) * QKVn + h * HDn + d4;
            float4 qv = sum2b(g_qkvp, base, SQ, bqkv, h * HDn + d4);
            s->qs[c * 65 + d4 + 0] = qv.x; s->qs[c * 65 + d4 + 1] = qv.y;
            s->qs[c * 65 + d4 + 2] = qv.z; s->qs[c * 65 + d4 + 3] = qv.w;
        }
        __syncthreads();
        #pragma unroll
        for (int r = 0; r < 4; r++) {
            int i = tid + r * 128;
            int k = i & 31, q = i >> 5;
            float sum = 0.f;
            #pragma unroll
            for (int d = 0; d < HDn; d++) { sum = fmaf(s->qs[q * 65 + d], s->ks[k * 65 + d], sum); }
            s->sc[q * 33 + k] = sum * 0.125f;
        }
        __syncthreads();
        if (tid < 16) {
            float mx = -1e30f;
            #pragma unroll
            for (int k = 0; k < Cn; k++) { mx = fmaxf(mx, s->sc[tid * 33 + k]); }
            float sum = 0.f;
            #pragma unroll
            for (int k = 0; k < Cn; k++) {
                float e = expf(s->sc[tid * 33 + k] - mx);
                s->sc[tid * 33 + k] = e;
                sum += e;
            }
            float inv = 1.f / sum;
            #pragma unroll
            for (int k = 0; k < Cn; k++) { s->sc[tid * 33 + k] *= inv; }
        }
        __syncthreads();
        #pragma unroll
        for (int r = 0; r < 8; r++) {
            int i = tid + r * 128;
            int d = i & 63, q = i >> 6;
            float sum = 0.f;
            #pragma unroll
            for (int k = 0; k < Cn; k++) { sum = fmaf(s->sc[q * 33 + k], s->vs[k * 65 + d], sum); }
            splitw(sum, g_attH, g_attL, (size_t)(b * Cn + q0 + q) * Rn + h * HDn + d);
        }
        __syncthreads();   // smem reused by next unit
    }
}

// ---------------- LayerNorm worker: one warp per row ----------------
template <int NPA, int NPP, bool WF32>
__device__ void ln_phase(const float* __restrict__ a, const float* __restrict__ ab,
                         const float* __restrict__ p, const float* __restrict__ pb,
                         const float* __restrict__ g, const float* __restrict__ be,
                         float* __restrict__ outF,
                         unsigned short* __restrict__ outH, unsigned short* __restrict__ outL) {
    int row = blockIdx.x * (NTHR / 32) + (threadIdx.x >> 5);
    if (row >= BC) { return; }
    const size_t S = (size_t)BC * Rn;
    int lane = threadIdx.x & 31;
    float v[8];
    #pragma unroll
    for (int j = 0; j < 8; j++) {
        int c = lane + 32 * j;
        size_t o = (size_t)row * Rn + c;
        float x = a[o];
        if (NPA >= 4) { x += a[S + o] + a[2 * S + o] + a[3 * S + o]; }
        if (NPA >= 8) {
            #pragma unroll
            for (int z = 4; z < 8; z++) { x += a[(size_t)z * S + o]; }
        }
        if (NPA > 1) { x += ab[c]; }
        float y = p[o];
        if (NPP >= 2) { y += p[S + o]; }
        if (NPP >= 4) { y += p[2 * S + o] + p[3 * S + o]; }
        if (NPP >= 8) {
            #pragma unroll
            for (int z = 4; z < 8; z++) { y += p[(size_t)z * S + o]; }
        }
        v[j] = x + y + pb[c];
    }
    float sum = 0.f;
    #pragma unroll
    for (int j = 0; j < 8; j++) { sum += v[j]; }
    #pragma unroll
    for (int off = 16; off > 0; off >>= 1) { sum += __shfl_xor_sync(0xffffffffu, sum, off); }
    float mean = sum * (1.f / Rn);
    float q = 0.f;
    #pragma unroll
    for (int j = 0; j < 8; j++) { float d = v[j] - mean; q = fmaf(d, d, q); }
    #pragma unroll
    for (int off = 16; off > 0; off >>= 1) { q += __shfl_xor_sync(0xffffffffu, q, off); }
    float rstd = rsqrtf(q * (1.f / Rn) + 1e-5f);
    #pragma unroll
    for (int j = 0; j < 8; j++) {
        int c = lane + 32 * j;
        float r = (v[j] - mean) * rstd * g[c] + be[c];
        size_t o = (size_t)row * Rn + c;
        if (WF32) { outF[o] = r; }
        splitw(r, outH, outL, o);
    }
}

// ---------------- megakernel ----------------
__global__ __launch_bounds__(NTHR, 4)
void mega_kernel(const float* __restrict__ embs, const int* __restrict__ indices,
                 const int* __restrict__ mask, const float* __restrict__ host_cat,
                 const float* __restrict__ virus_cat, const float* __restrict__ extra_meta,
                 const float* __restrict__ fw,
                 const float* __restrict__ Wr, const float* __restrict__ br,
                 const float* __restrict__ Wqkv, const float* __restrict__ bqkv,
                 const float* __restrict__ Wo, const float* __restrict__ bo,
                 const float* __restrict__ ln1_g, const float* __restrict__ ln1_b,
                 const float* __restrict__ W1, const float* __restrict__ b1,
                 const float* __restrict__ W2, const float* __restrict__ b2,
                 const float* __restrict__ ln2_g, const float* __restrict__ ln2_b,
                 const float* __restrict__ Wc1, const float* __restrict__ bc1,
                 const float* __restrict__ Wc2, const float* __restrict__ bc2,
                 float* __restrict__ out) {
    __shared__ SmemU sm;
    __shared__ float s_red[4];
    __shared__ float s_aw[Sn];
    const int tid = threadIdx.x;
    const int grp = blockIdx.x;
    const int gid = blockIdx.x * NTHR + tid;
    const int lane = tid & 31;

    // ---- P0: aggregation, segment-major (softmax computed ONCE per segment) ----
    for (int seg = grp; seg < BC; seg += NGRP) {
        if (tid < 32) {
            int s16 = lane & 15;
            int mval = mask[seg * Sn + s16];
            float wv = mval ? fw[indices[seg * Sn + s16]] : -1e30f;
            unsigned anyb = __ballot_sync(0xffffffffu, mval != 0);
            float mx = wv;
            #pragma unroll
            for (int off = 8; off > 0; off >>= 1) { mx = fmaxf(mx, __shfl_xor_sync(0xffffffffu, mx, off)); }
            float e = expf(wv - mx);
            float esum = e;
            #pragma unroll
            for (int off = 8; off > 0; off >>= 1) { esum += __shfl_xor_sync(0xffffffffu, esum, off); }
            float myw = (anyb & 0xffffu) ? (e / esum) : 0.f;
            if (lane < 16) { s_aw[lane] = myw; }
        }
        __syncthreads();
        float w[Sn];
        #pragma unroll
        for (int s = 0; s < Sn; s++) { w[s] = s_aw[s]; }
        const float4* eb = (const float4*)embs + (size_t)seg * Sn * (En / 4);
        for (int col = tid; col < En / 4; col += NTHR) {
            float4 acc;
            acc.x = 0.f; acc.y = 0.f; acc.z = 0.f; acc.w = 0.f;
            #pragma unroll
            for (int s = 0; s < Sn; s++) {
                float4 v = eb[s * (En / 4) + col];
                acc.x = fmaf(w[s], v.x, acc.x);
                acc.y = fmaf(w[s], v.y, acc.y);
                acc.z = fmaf(w[s], v.z, acc.z);
                acc.w = fmaf(w[s], v.w, acc.w);
            }
            uint2 hi, lo;
            split4(acc, hi, lo);
            *(uint2*)(g_aggH + (size_t)seg * En + col * 4) = hi;
            *(uint2*)(g_aggL + (size_t)seg * En + col * 4) = lo;
        }
        __syncthreads();   // s_aw reused by next segment
    }
    conv_w(Wr, g_WrH, g_WrL, Rn * En / 4, gid, NBLK * NTHR);
    gsync(0);

    // ---- P2: x0 partials = agg @ Wr^T (SS, split 8, KS=160, 5 chunks, 512 tiles) ----
    gemm_ss(g_aggH, g_aggL, g_WrH, g_WrL, g_x0p, Rn, En, 16, 4, 8, 160, BC, &sm.g, tid, grp);
    if (grp >= 512) {   // idle groups convert Wqkv (needed at P3)
        conv_w(Wqkv, g_WqH, g_WqL, QKVn * Rn / 4, (grp - 512) * NTHR + tid, 80 * NTHR);
    }
    gsync(1);

    // ---- R1: x0 = sum8(x0p) + br  -> fp32 + bf16 split ----
    {
        constexpr size_t S = (size_t)BC * Rn;
        for (int i = gid; i < BC * Rn / 4; i += NBLK * NTHR) {
            size_t o = (size_t)i * 4;
            float4 v = *(const float4*)(g_x0p + o);
            #pragma unroll
            for (int z = 1; z < 8; z++) {
                float4 t = *(const float4*)(g_x0p + (size_t)z * S + o);
                v.x += t.x; v.y += t.y; v.z += t.z; v.w += t.w;
            }
            float4 bb = *(const float4*)(br + (i & 63) * 4);
            v.x += bb.x; v.y += bb.y; v.z += bb.z; v.w += bb.w;
            *(float4*)(g_x0 + o) = v;
            uint2 hi, lo;
            split4(v, hi, lo);
            *(uint2*)(g_x0H + o) = hi;
            *(uint2*)(g_x0L + o) = lo;
        }
    }
    gsync(2);

    // ---- P3: qkv partials = x0 @ Wqkv^T (SS, split 2, KS=128, 384 tiles) ----
    gemm_ss(g_x0H, g_x0L, g_WqH, g_WqL, g_qkvp, QKVn, Rn, 16, 12, 2, 128, BC, &sm.g, tid, grp);
    if (grp >= 384) {   // idle groups convert Wo (needed at P5)
        conv_w(Wo, g_WoH, g_WoL, Rn * Rn / 4, (grp - 384) * NTHR + tid, 208 * NTHR);
    }
    gsync(3);

    // ---- P4: attention (256 units); idle groups convert W1, W2, Wc1 ----
    attn_phase(&sm.a, bqkv, tid, grp);
    if (grp >= 256) {
        int base = (grp - 256) * NTHR + tid;
        int stride = 336 * NTHR;
        conv_w(W1, g_W1H, g_W1L, FFn * Rn / 4, base, stride);
        conv_w(W2, g_W2H, g_W2L, Rn * FFn / 4, base, stride);
        for (int i = base; i < 128 * (HK / 4); i += stride) {
            int row = i >> 11;
            int c4 = (i & 2047) * 4;
            const float* sp = Wc1 + (size_t)row * HEAD_IN + c4;
            float4 v;
            v.x = sp[0]; v.y = sp[1]; v.z = sp[2]; v.w = sp[3];
            uint2 hi, lo;
            split4(v, hi, lo);
            *(uint2*)(g_WcH + (size_t)row * HK + c4) = hi;
            *(uint2*)(g_WcL + (size_t)row * HK + c4) = lo;
        }
    }
    gsync(4);

    // ---- P5: oproj partials = att @ Wo^T (SS, split 8, KS=32, 1 chunk, 512 tiles) ----
    gemm_ss(g_attH, g_attL, g_WoH, g_WoL, g_opp, Rn, Rn, 16, 4, 8, 32, BC, &sm.g, tid, grp);
    gsync(5);

    // ---- P6: x1 = LN(x0 + sum8 opp + bo), write fp32 + split ----
    ln_phase<1, 8, true>(g_x0, (const float*)0, g_opp, bo, ln1_g, ln1_b, g_x1, g_x1H, g_x1L);
    gsync(6);

    // ---- P7: ff1 partials = x1 @ W1^T (SS, split 4, KS=64, 2 chunks, 512 tiles) ----
    gemm_ss(g_x1H, g_x1L, g_W1H, g_W1L, g_ff1p, FFn, Rn, 16, 8, 4, 64, BC, &sm.g, tid, grp);
    gsync(7);

    // ---- R2: ff1s = relu(sum4(ff1p) + b1) -> bf16 split ----
    {
        constexpr size_t S = (size_t)BC * FFn;
        for (int i = gid; i < BC * FFn / 4; i += NBLK * NTHR) {
            size_t o = (size_t)i * 4;
            float4 v = *(const float4*)(g_ff1p + o);
            #pragma unroll
            for (int z = 1; z < 4; z++) {
                float4 t = *(const float4*)(g_ff1p + (size_t)z * S + o);
                v.x += t.x; v.y += t.y; v.z += t.z; v.w += t.w;
            }
            float4 bb = *(const float4*)(b1 + (i & 127) * 4);
            v.x = fmaxf(v.x + bb.x, 0.f);
            v.y = fmaxf(v.y + bb.y, 0.f);
            v.z = fmaxf(v.z + bb.z, 0.f);
            v.w = fmaxf(v.w + bb.w, 0.f);
            uint2 hi, lo;
            split4(v, hi, lo);
            *(uint2*)(g_ff1H + o) = hi;
            *(uint2*)(g_ff1L + o) = lo;
        }
    }
    gsync(8);

    // ---- P8: ff2 partials = ff1s @ W2^T (SS, split 8, KS=64, 2 chunks, 512 tiles) ----
    gemm_ss(g_ff1H, g_ff1L, g_W2H, g_W2L, g_fpp, Rn, FFn, 16, 4, 8, 64, BC, &sm.g, tid, grp);
    gsync(9);

    // ---- P9: x2 = LN(x1 + sum8 fpp + b2) -> feat split rows 0-31 ([32, 8192] flat) ----
    ln_phase<1, 8, false>(g_x1, (const float*)0, g_fpp, b2, ln2_g, ln2_b,
                          (float*)0, g_featH, g_featL);
    gsync(10);

    // ---- P10: head GEMM: hp = feat[64, 8192] @ Wc1h[128, 8192]^T (SS, split 128, KS=64) ----
    gemm_ss(g_featH, g_featL, g_WcH, g_WcL, g_hp, 128, HK, 1, 2, 128, 64, 64, &sm.g, tid, grp);
    gsync(11);

    // ---- P11: head reduce + tail + bias + relu + logits (block b = batch b) ----
    if (grp < Bn) {
        int b = grp;
        int j = tid;
        float s = 0.f;
        #pragma unroll 16
        for (int z = 0; z < 128; z++) { s += g_hp[(size_t)z * (64 * 128) + b * 128 + j]; }
        const float* wr = Wc1 + (size_t)j * HEAD_IN + HK;
        const float* hc = host_cat + b * 64;
        #pragma unroll 8
        for (int i = 0; i < 64; i++) { s = fmaf(wr[i], hc[i], s); }
        const float* vc = virus_cat + b * 32;
        #pragma unroll 8
        for (int i = 0; i < 32; i++) { s = fmaf(wr[64 + i], vc[i], s); }
        const float* mt = extra_meta + b * 3;
        for (int i = 0; i < 3; i++) { s = fmaf(wr[96 + i], mt[i], s); }
        float hval = fmaxf(s + bc1[j], 0.f);
        float v = hval * Wc2[j];
        #pragma unroll
        for (int off = 16; off > 0; off >>= 1) { v += __shfl_xor_sync(0xffffffffu, v, off); }
        if (lane == 0) { s_red[tid >> 5] = v; }
        __syncthreads();
        if (tid == 0) { out[b] = s_red[0] + s_red[1] + s_red[2] + s_red[3] + bc2[0]; }
    }
}

// ---------------- launch ----------------
extern "C" void kernel_launch(void* const* d_in, const int* in_sizes, int n_in,
                              void* d_out, int out_size) {
    const float* embs        = (const float*)d_in[0];
    const int*   indices     = (const int*)d_in[1];
    const int*   mask        = (const int*)d_in[2];     // bool -> int32
    const float* host_cat    = (const float*)d_in[3];
    const float* virus_cat   = (const float*)d_in[4];
    const float* extra_meta  = (const float*)d_in[5];
    const float* func_weights= (const float*)d_in[6];
    const float* Wr          = (const float*)d_in[7];
    const float* br          = (const float*)d_in[8];
    const float* Wqkv        = (const float*)d_in[9];
    const float* bqkv        = (const float*)d_in[10];
    const float* Wo          = (const float*)d_in[11];
    const float* bo          = (const float*)d_in[12];
    const float* ln1_g       = (const float*)d_in[13];
    const float* ln1_b       = (const float*)d_in[14];
    const float* W1          = (const float*)d_in[15];
    const float* b1          = (const float*)d_in[16];
    const float* W2          = (const float*)d_in[17];
    const float* b2          = (const float*)d_in[18];
    const float* ln2_g       = (const float*)d_in[19];
    const float* ln2_b       = (const float*)d_in[20];
    const float* Wc1         = (const float*)d_in[21];
    const float* bc1         = (const float*)d_in[22];
    const float* Wc2         = (const float*)d_in[23];
    const float* bc2         = (const float*)d_in[24];
    float* out = (float*)d_out;

    mega_kernel<<<NBLK, NTHR>>>(embs, indices, mask, host_cat, virus_cat, extra_meta,
                                func_weights, Wr, br, Wqkv, bqkv, Wo, bo,
                                ln1_g, ln1_b, W1, b1, W2, b2, ln2_g, ln2_b,
                                Wc1, bc1, Wc2, bc2, out);
}